// round 11
// baseline (speedup 1.0000x reference)
#include <cuda_runtime.h>
#include <math.h>
#include <stdint.h>

// ---------------------------------------------------------------------------
// Problem constants
// ---------------------------------------------------------------------------
namespace {
constexpr int B_  = 16384;
constexpr int SD  = 128;
constexpr int EK  = 10;
constexpr int K1  = SD * EK;   // 1280
constexpr int H   = 2048;
constexpr int N3  = 320;
constexpr int AD  = 32;
constexpr int DK  = 10;

constexpr int BM = 128;

// GEMM3 (small-N) kernel tiling
constexpr int BK3  = 32;
constexpr int LDA3 = BK3 + 4;      // 36
// Big GEMM tiling
constexpr int BKB  = 64;
constexpr int LDB  = BKB + 4;      // 68
constexpr int STAGES = 3;

constexpr int TBL    = 4096;
constexpr float TRNG = 14.0f;
}

// Scratch (no cudaMalloc allowed)
__device__ float g_spine[B_ * K1];
__device__ float g_h1[B_ * H];
__device__ float g_h2[B_ * H];
__device__ float g_a3[B_ * N3];
__device__ float g_w1[H * K1];
__device__ float g_w2[H * H];
__device__ float g_w3[N3 * H];
__device__ float g_table[TBL + 1];
__device__ float g_rstd[K1];

// ---------------------------------------------------------------------------
// PTX helpers (sm_80+ only — harness targets compute_100, no tcgen05)
// ---------------------------------------------------------------------------
__device__ __forceinline__ uint32_t smem_u32(const void* p) {
    uint32_t a;
    asm("{ .reg .u64 t; cvta.to.shared.u64 t, %1; cvt.u32.u64 %0, t; }"
        : "=r"(a) : "l"(p));
    return a;
}
__device__ __forceinline__ void cp_async16(uint32_t dst, const void* src) {
    asm volatile("cp.async.cg.shared.global [%0], [%1], 16;\n"
                 :: "r"(dst), "l"(src));
}
__device__ __forceinline__ void cp_commit() {
    asm volatile("cp.async.commit_group;\n" ::: "memory");
}
template <int N>
__device__ __forceinline__ void cp_wait_group() {
    asm volatile("cp.async.wait_group %0;\n" :: "n"(N) : "memory");
}
__device__ __forceinline__ float cvt_tf32_f(float x) {
    uint32_t r;
    asm("cvt.rna.tf32.f32 %0, %1;" : "=r"(r) : "f"(x));
    return __uint_as_float(r);
}
__device__ __forceinline__ void ldsm_x4(uint32_t& r0, uint32_t& r1,
                                        uint32_t& r2, uint32_t& r3,
                                        uint32_t addr) {
    asm volatile(
        "ldmatrix.sync.aligned.m8n8.x4.shared.b16 {%0,%1,%2,%3}, [%4];"
        : "=r"(r0), "=r"(r1), "=r"(r2), "=r"(r3) : "r"(addr));
}
// Operands pre-rounded to tf32 (RNA) in memory -> feed raw bits, HW RZ is identity.
__device__ __forceinline__ void mma_tf32(float* c, const uint32_t* a,
                                         const uint32_t* b) {
    asm volatile(
        "mma.sync.aligned.m16n8k8.row.col.f32.tf32.tf32.f32 "
        "{%0,%1,%2,%3}, {%4,%5,%6,%7}, {%8,%9}, {%0,%1,%2,%3};"
        : "+f"(c[0]), "+f"(c[1]), "+f"(c[2]), "+f"(c[3])
        : "r"(a[0]), "r"(a[1]), "r"(a[2]), "r"(a[3]), "r"(b[0]), "r"(b[1]));
}

// ---------------------------------------------------------------------------
// Init: sigmoid table + reciprocal std
// ---------------------------------------------------------------------------
__global__ void init_tables_kernel(const float* __restrict__ stdv) {
    const int i = blockIdx.x * blockDim.x + threadIdx.x;
    if (i <= TBL) {
        const float x = -TRNG + (2.0f * TRNG) * (float)i / (float)TBL;
        g_table[i] = 1.0f / (1.0f + expf(-x));
    }
    if (i < K1) g_rstd[i] = 1.0f / stdv[i];
}

// ---------------------------------------------------------------------------
// RNA-round weights into scratch (once per launch)
// ---------------------------------------------------------------------------
__global__ __launch_bounds__(256) void round_weights_kernel(
    const float* __restrict__ w1, const float* __restrict__ w2,
    const float* __restrict__ w3)
{
    constexpr int N1 = H * K1, N2 = H * H, N3E = N3 * H;
    const int stride = gridDim.x * blockDim.x;
    for (int i = blockIdx.x * blockDim.x + threadIdx.x; i < N1 / 4; i += stride) {
        float4 v = reinterpret_cast<const float4*>(w1)[i];
        v.x = cvt_tf32_f(v.x); v.y = cvt_tf32_f(v.y);
        v.z = cvt_tf32_f(v.z); v.w = cvt_tf32_f(v.w);
        reinterpret_cast<float4*>(g_w1)[i] = v;
    }
    for (int i = blockIdx.x * blockDim.x + threadIdx.x; i < N2 / 4; i += stride) {
        float4 v = reinterpret_cast<const float4*>(w2)[i];
        v.x = cvt_tf32_f(v.x); v.y = cvt_tf32_f(v.y);
        v.z = cvt_tf32_f(v.z); v.w = cvt_tf32_f(v.w);
        reinterpret_cast<float4*>(g_w2)[i] = v;
    }
    for (int i = blockIdx.x * blockDim.x + threadIdx.x; i < N3E / 4; i += stride) {
        float4 v = reinterpret_cast<const float4*>(w3)[i];
        v.x = cvt_tf32_f(v.x); v.y = cvt_tf32_f(v.y);
        v.z = cvt_tf32_f(v.z); v.w = cvt_tf32_f(v.w);
        reinterpret_cast<float4*>(g_w3)[i] = v;
    }
}

// ---------------------------------------------------------------------------
// Encoder: spine = tf32_rna(sigmoid((state - mean) * rstd)) via interp table
// ---------------------------------------------------------------------------
__global__ __launch_bounds__(256) void encode_kernel(
    const float* __restrict__ state, const float* __restrict__ mean,
    float* __restrict__ spine)
{
    __shared__ float tbl[TBL + 4];
    __shared__ float s_mean[K1];
    __shared__ float s_rstd[K1];
    for (int i = threadIdx.x; i <= TBL; i += 256) tbl[i] = g_table[i];
    for (int i = threadIdx.x; i < K1; i += 256) {
        s_mean[i] = mean[i];
        s_rstd[i] = g_rstd[i];
    }
    __syncthreads();

    constexpr float SCALE = (float)TBL / (2.0f * TRNG);
    const int total4 = B_ * K1 / 4;
    for (int idx4 = blockIdx.x * blockDim.x + threadIdx.x; idx4 < total4;
         idx4 += gridDim.x * blockDim.x) {
        const int base = idx4 * 4;
        const int b  = base / K1;
        const int k0 = base - b * K1;
        float4 o;
        float* op = reinterpret_cast<float*>(&o);
        #pragma unroll
        for (int j = 0; j < 4; j++) {
            const int k = k0 + j;
            const int d = k / EK;
            const float x = (state[b * SD + d] - s_mean[k]) * s_rstd[k];
            float t = (x + TRNG) * SCALE;
            t = fminf(fmaxf(t, 0.0f), (float)TBL - 0.0001f);
            const int i = (int)t;
            const float f = t - (float)i;
            op[j] = cvt_tf32_f(fmaf(f, tbl[i + 1] - tbl[i], tbl[i]));
        }
        *reinterpret_cast<float4*>(&spine[base]) = o;
    }
}

// ---------------------------------------------------------------------------
// BIG GEMM (layers 1/2): BK=64 (half the chunk barriers), 256 threads,
//   8 warps 2x4 (warp tile 64x32), 3-stage cp.async pipeline (204KB smem,
//   1 CTA/SM), and EXPLICIT fragment double-buffering across kk-steps.
// ---------------------------------------------------------------------------
template <int NDIM, int KDIM, bool RELU, bool ROUND_OUT>
__global__ __launch_bounds__(256, 1) void gemm_big(
    const float* __restrict__ A, const float* __restrict__ W,
    const float* __restrict__ bias, float* __restrict__ out)
{
    constexpr int BN = 128;
    constexpr int STRIDE = (BM + BN) * LDB;   // floats per stage
    constexpr int NT = 4;                     // 8-wide n-tiles per warp
    constexpr int nK = KDIM / BKB;
    constexpr int KKS = BKB / 8;              // 8 kk-steps per chunk
    extern __shared__ float sm[];

    const int tid  = threadIdx.x;
    const int lane = tid & 31;
    const int wid  = tid >> 5;                // 0..7
    const int bm = blockIdx.y * BM;
    const int bn = blockIdx.x * BN;
    const int wm = (wid >> 2) * 64;
    const int wn = (wid & 3) * 32;
    const int ar = lane >> 2;
    const int ac = lane & 3;

    const uint32_t smb = smem_u32(sm);
    const uint32_t a_lane = smb +
        4u * ((wm + ((lane >> 3) & 1) * 8 + (lane & 7)) * LDB + (lane >> 4) * 4);
    const uint32_t b_lane = smb + 4u * (BM * LDB) +
        4u * ((wn + (lane >> 4) * 8 + (lane & 7)) * LDB + ((lane >> 3) & 1) * 4);

    float acc[4][NT][4];
    #pragma unroll
    for (int i = 0; i < 4; i++)
        #pragma unroll
        for (int j = 0; j < NT; j++)
            #pragma unroll
            for (int m = 0; m < 4; m++) acc[i][j][m] = 0.0f;

    auto load_stage = [&](int s, int kc) {
        float* As = sm + s * STRIDE;
        float* Bs = As + BM * LDB;
        const int k0 = kc * BKB;
        // A: BM rows x 16 chunks of 16B
        #pragma unroll 8
        for (int q = tid; q < BM * 16; q += 256) {
            const int r = q >> 4, c = q & 15;
            cp_async16(smem_u32(As + r * LDB + c * 4),
                       A + (size_t)(bm + r) * KDIM + k0 + c * 4);
        }
        #pragma unroll 8
        for (int q = tid; q < BN * 16; q += 256) {
            const int r = q >> 4, c = q & 15;
            cp_async16(smem_u32(Bs + r * LDB + c * 4),
                       W + (size_t)(bn + r) * KDIM + k0 + c * 4);
        }
    };

    #pragma unroll
    for (int s = 0; s < STAGES - 1; s++) { load_stage(s, s); cp_commit(); }

    uint32_t af[2][4][4], bf[2][NT][2];

    auto load_frags = [&](int buf, uint32_t stg, int kk) {
        #pragma unroll
        for (int tm = 0; tm < 4; tm++)
            ldsm_x4(af[buf][tm][0], af[buf][tm][1], af[buf][tm][2], af[buf][tm][3],
                    a_lane + stg + (uint32_t)(tm * 16 * LDB + kk * 8) * 4);
        #pragma unroll
        for (int tp = 0; tp < NT / 2; tp++)
            ldsm_x4(bf[buf][tp * 2][0], bf[buf][tp * 2][1],
                    bf[buf][tp * 2 + 1][0], bf[buf][tp * 2 + 1][1],
                    b_lane + stg + (uint32_t)(tp * 16 * LDB + kk * 8) * 4);
    };

    for (int k = 0; k < nK; k++) {
        cp_wait_group<STAGES - 2>();
        __syncthreads();

        // Issue next-stage cp.async first (2-chunk latency slack).
        const int kn = k + STAGES - 1;
        if (kn < nK) load_stage(kn % STAGES, kn);
        cp_commit();

        const uint32_t stg = (uint32_t)((k % STAGES) * STRIDE * 4);
        load_frags(0, stg, 0);
        #pragma unroll
        for (int kk = 0; kk < KKS; kk++) {
            const int cb = kk & 1;
            if (kk + 1 < KKS) load_frags(cb ^ 1, stg, kk + 1);
            #pragma unroll
            for (int tm = 0; tm < 4; tm++)
                #pragma unroll
                for (int tn = 0; tn < NT; tn++)
                    mma_tf32(acc[tm][tn], af[cb][tm], bf[cb][tn]);
        }
    }

    // Epilogue: bias + activation (+ optional tf32 rounding), float2 stores.
    #pragma unroll
    for (int tm = 0; tm < 4; tm++) {
        const int row0 = bm + wm + tm * 16 + ar;
        #pragma unroll
        for (int tn = 0; tn < NT; tn++) {
            const int col = bn + wn + tn * 8 + ac * 2;
            const float bx = bias[col];
            const float by = bias[col + 1];
            float* c = acc[tm][tn];
            float2 v0, v1;
            v0.x = c[0] + bx; v0.y = c[1] + by;
            v1.x = c[2] + bx; v1.y = c[3] + by;
            if (RELU) {
                v0.x = v0.x > 0.0f ? v0.x : 0.0f;
                v0.y = v0.y > 0.0f ? v0.y : 0.0f;
                v1.x = v1.x > 0.0f ? v1.x : 0.0f;
                v1.y = v1.y > 0.0f ? v1.y : 0.0f;
            }
            if (ROUND_OUT) {
                v0.x = cvt_tf32_f(v0.x); v0.y = cvt_tf32_f(v0.y);
                v1.x = cvt_tf32_f(v1.x); v1.y = cvt_tf32_f(v1.y);
            }
            *reinterpret_cast<float2*>(&out[(size_t)row0 * NDIM + col]) = v0;
            *reinterpret_cast<float2*>(&out[(size_t)(row0 + 8) * NDIM + col]) = v1;
        }
    }
}

// ---------------------------------------------------------------------------
// GEMM3 (N3=320): proven 256-thread BK=32 config, warp tile 64x16.
// ---------------------------------------------------------------------------
template <int BN, int NDIM, int KDIM, bool RELU, bool ROUND_OUT>
__global__ __launch_bounds__(256, 2) void gemm_mma(
    const float* __restrict__ A, const float* __restrict__ W,
    const float* __restrict__ bias, float* __restrict__ out)
{
    constexpr int STRIDE = (BM + BN) * LDA3;
    constexpr int NT = BN / 32;
    constexpr int NP = NT / 2;
    constexpr int nK = KDIM / BK3;
    extern __shared__ float sm[];

    const int tid  = threadIdx.x;
    const int lane = tid & 31;
    const int wid  = tid >> 5;
    const int bm = blockIdx.y * BM;
    const int bn = blockIdx.x * BN;
    const int wm = (wid >> 2) * 64;
    const int wn = (wid & 3) * (BN / 4);
    const int ar = lane >> 2;
    const int ac = lane & 3;

    const uint32_t smb = smem_u32(sm);
    const uint32_t a_lane = smb +
        4u * ((wm + ((lane >> 3) & 1) * 8 + (lane & 7)) * LDA3 + (lane >> 4) * 4);
    const uint32_t b_lane = smb + 4u * (BM * LDA3) +
        4u * ((wn + (lane >> 4) * 8 + (lane & 7)) * LDA3 + ((lane >> 3) & 1) * 4);

    float acc[4][NT][4];
    #pragma unroll
    for (int i = 0; i < 4; i++)
        #pragma unroll
        for (int j = 0; j < NT; j++)
            #pragma unroll
            for (int m = 0; m < 4; m++) acc[i][j][m] = 0.0f;

    auto load_stage = [&](int s, int kc) {
        float* As = sm + s * STRIDE;
        float* Bs = As + BM * LDA3;
        const int k0 = kc * BK3;
        #pragma unroll 4
        for (int q = tid; q < BM * 8; q += 256) {
            const int r = q >> 3, c = q & 7;
            cp_async16(smem_u32(As + r * LDA3 + c * 4),
                       A + (size_t)(bm + r) * KDIM + k0 + c * 4);
        }
        #pragma unroll 4
        for (int q = tid; q < BN * 8; q += 256) {
            const int r = q >> 3, c = q & 7;
            cp_async16(smem_u32(Bs + r * LDA3 + c * 4),
                       W + (size_t)(bn + r) * KDIM + k0 + c * 4);
        }
    };

    #pragma unroll
    for (int s = 0; s < STAGES - 1; s++) { load_stage(s, s); cp_commit(); }

    for (int k = 0; k < nK; k++) {
        cp_wait_group<STAGES - 2>();
        __syncthreads();

        const int kn = k + STAGES - 1;
        if (kn < nK) load_stage(kn % STAGES, kn);
        cp_commit();

        const uint32_t stg = (uint32_t)((k % STAGES) * STRIDE * 4);
        #pragma unroll
        for (int kk = 0; kk < BK3 / 8; kk++) {
            uint32_t af[4][4], bf[NT][2];
            #pragma unroll
            for (int tm = 0; tm < 4; tm++)
                ldsm_x4(af[tm][0], af[tm][1], af[tm][2], af[tm][3],
                        a_lane + stg + (uint32_t)(tm * 16 * LDA3 + kk * 8) * 4);
            #pragma unroll
            for (int tp = 0; tp < NP; tp++)
                ldsm_x4(bf[tp * 2][0], bf[tp * 2][1],
                        bf[tp * 2 + 1][0], bf[tp * 2 + 1][1],
                        b_lane + stg + (uint32_t)(tp * 16 * LDA3 + kk * 8) * 4);
            #pragma unroll
            for (int tm = 0; tm < 4; tm++)
                #pragma unroll
                for (int tn = 0; tn < NT; tn++)
                    mma_tf32(acc[tm][tn], af[tm], bf[tn]);
        }
    }

    #pragma unroll
    for (int tm = 0; tm < 4; tm++) {
        const int row0 = bm + wm + tm * 16 + ar;
        #pragma unroll
        for (int tn = 0; tn < NT; tn++) {
            const int col = bn + wn + tn * 8 + ac * 2;
            const float bx = bias[col];
            const float by = bias[col + 1];
            float* c = acc[tm][tn];
            float2 v0, v1;
            v0.x = c[0] + bx; v0.y = c[1] + by;
            v1.x = c[2] + bx; v1.y = c[3] + by;
            if (RELU) {
                v0.x = v0.x > 0.0f ? v0.x : 0.0f;
                v0.y = v0.y > 0.0f ? v0.y : 0.0f;
                v1.x = v1.x > 0.0f ? v1.x : 0.0f;
                v1.y = v1.y > 0.0f ? v1.y : 0.0f;
            }
            if (ROUND_OUT) {
                v0.x = cvt_tf32_f(v0.x); v0.y = cvt_tf32_f(v0.y);
                v1.x = cvt_tf32_f(v1.x); v1.y = cvt_tf32_f(v1.y);
            }
            *reinterpret_cast<float2*>(&out[(size_t)row0 * NDIM + col]) = v0;
            *reinterpret_cast<float2*>(&out[(size_t)(row0 + 8) * NDIM + col]) = v1;
        }
    }
}

// ---------------------------------------------------------------------------
// Decoder: out[b,a] = tanh(sum_j a3[b, a*DK+j] * Wd[a*DK+j] + bd[a])
// ---------------------------------------------------------------------------
__global__ __launch_bounds__(256) void decode_kernel(
    const float* __restrict__ a3, const float* __restrict__ Wd,
    const float* __restrict__ bd, float* __restrict__ out)
{
    const int idx = blockIdx.x * blockDim.x + threadIdx.x;
    if (idx >= B_ * AD) return;
    const int b = idx >> 5;
    const int a = idx & 31;
    float s = bd[a];
    #pragma unroll
    for (int j = 0; j < DK; j++)
        s = fmaf(a3[b * N3 + a * DK + j], Wd[a * DK + j], s);
    out[idx] = tanhf(s);
}

// ---------------------------------------------------------------------------
extern "C" void kernel_launch(void* const* d_in, const int* in_sizes, int n_in,
                              void* d_out, int out_size)
{
    const float* state = (const float*)d_in[0];
    const float* mean  = (const float*)d_in[1];
    const float* stdv  = (const float*)d_in[2];
    const float* W1    = (const float*)d_in[3];
    const float* b1    = (const float*)d_in[4];
    const float* W2    = (const float*)d_in[5];
    const float* b2    = (const float*)d_in[6];
    const float* W3    = (const float*)d_in[7];
    const float* b3    = (const float*)d_in[8];
    const float* Wd    = (const float*)d_in[9];
    const float* bd    = (const float*)d_in[10];
    float* out = (float*)d_out;

    float *spine, *h1, *h2, *a3, *w1r, *w2r, *w3r;
    cudaGetSymbolAddress((void**)&spine, g_spine);
    cudaGetSymbolAddress((void**)&h1, g_h1);
    cudaGetSymbolAddress((void**)&h2, g_h2);
    cudaGetSymbolAddress((void**)&a3, g_a3);
    cudaGetSymbolAddress((void**)&w1r, g_w1);
    cudaGetSymbolAddress((void**)&w2r, g_w2);
    cudaGetSymbolAddress((void**)&w3r, g_w3);

    constexpr int SMEM_BIG = STAGES * (BM + 128) * LDB * sizeof(float); // 208896
    constexpr int SMEM_G3  = STAGES * (BM + 64) * LDA3 * sizeof(float); //  82944
    static bool attr_done = false;
    if (!attr_done) {
        cudaFuncSetAttribute(gemm_big<H, K1, true, true>,
                             cudaFuncAttributeMaxDynamicSharedMemorySize, SMEM_BIG);
        cudaFuncSetAttribute(gemm_big<H, H, true, true>,
                             cudaFuncAttributeMaxDynamicSharedMemorySize, SMEM_BIG);
        cudaFuncSetAttribute(gemm_mma<64, N3, H, false, false>,
                             cudaFuncAttributeMaxDynamicSharedMemorySize, SMEM_G3);
        attr_done = true;
    }

    init_tables_kernel<<<(TBL + 256) / 256, 256>>>(stdv);
    round_weights_kernel<<<1024, 256>>>(W1, W2, W3);
    encode_kernel<<<2048, 256>>>(state, mean, spine);

    gemm_big<H, K1, true, true>
        <<<dim3(H / 128, B_ / BM), 256, SMEM_BIG>>>(spine, w1r, b1, h1);
    gemm_big<H, H, true, true>
        <<<dim3(H / 128, B_ / BM), 256, SMEM_BIG>>>(h1, w2r, b2, h2);
    gemm_mma<64, N3, H, false, false>
        <<<dim3(N3 / 64, B_ / BM), 256, SMEM_G3>>>(h2, w3r, b3, a3);

    decode_kernel<<<(B_ * AD + 255) / 256, 256>>>(a3, Wd, bd, out);
}

// round 12
// speedup vs baseline: 2.1558x; 2.1558x over previous
#include <cuda_runtime.h>
#include <cuda_fp16.h>
#include <math.h>
#include <stdint.h>

// ---------------------------------------------------------------------------
// Problem constants
// ---------------------------------------------------------------------------
namespace {
constexpr int B_  = 16384;
constexpr int SD  = 128;
constexpr int EK  = 10;
constexpr int K1  = SD * EK;   // 1280
constexpr int H   = 2048;
constexpr int N3  = 320;
constexpr int AD  = 32;
constexpr int DK  = 10;

constexpr int BM  = 128;
constexpr int BK  = 64;            // halves per chunk (4 k16 steps)
constexpr int LDH = BK + 8;        // 72-half (144B) smem row stride: conflict-free
constexpr int STAGES = 3;

constexpr int TBL    = 4096;
constexpr float TRNG = 14.0f;
}

// Scratch (no cudaMalloc allowed)
__device__ __half g_spine[B_ * K1];
__device__ __half g_h1[B_ * H];
__device__ __half g_h2[B_ * H];
__device__ float  g_a3[B_ * N3];
__device__ __half g_w1[H * K1];
__device__ __half g_w2[H * H];
__device__ __half g_w3[N3 * H];
__device__ float  g_table[TBL + 1];
__device__ float  g_rstd[K1];

// ---------------------------------------------------------------------------
// PTX helpers (sm_80+ only — harness targets compute_100, no tcgen05)
// ---------------------------------------------------------------------------
__device__ __forceinline__ uint32_t smem_u32(const void* p) {
    uint32_t a;
    asm("{ .reg .u64 t; cvta.to.shared.u64 t, %1; cvt.u32.u64 %0, t; }"
        : "=r"(a) : "l"(p));
    return a;
}
__device__ __forceinline__ void cp_async16(uint32_t dst, const void* src) {
    asm volatile("cp.async.cg.shared.global [%0], [%1], 16;\n"
                 :: "r"(dst), "l"(src));
}
__device__ __forceinline__ void cp_commit() {
    asm volatile("cp.async.commit_group;\n" ::: "memory");
}
template <int N>
__device__ __forceinline__ void cp_wait_group() {
    asm volatile("cp.async.wait_group %0;\n" :: "n"(N) : "memory");
}
__device__ __forceinline__ void ldsm_x4(uint32_t& r0, uint32_t& r1,
                                        uint32_t& r2, uint32_t& r3,
                                        uint32_t addr) {
    asm volatile(
        "ldmatrix.sync.aligned.m8n8.x4.shared.b16 {%0,%1,%2,%3}, [%4];"
        : "=r"(r0), "=r"(r1), "=r"(r2), "=r"(r3) : "r"(addr));
}
// fp16 MMA, fp32 accumulate: m16n8k16
__device__ __forceinline__ void mma_f16(float* c, const uint32_t* a,
                                        const uint32_t* b) {
    asm volatile(
        "mma.sync.aligned.m16n8k16.row.col.f32.f16.f16.f32 "
        "{%0,%1,%2,%3}, {%4,%5,%6,%7}, {%8,%9}, {%0,%1,%2,%3};"
        : "+f"(c[0]), "+f"(c[1]), "+f"(c[2]), "+f"(c[3])
        : "r"(a[0]), "r"(a[1]), "r"(a[2]), "r"(a[3]), "r"(b[0]), "r"(b[1]));
}

// ---------------------------------------------------------------------------
// Init: sigmoid table + reciprocal std
// ---------------------------------------------------------------------------
__global__ void init_tables_kernel(const float* __restrict__ stdv) {
    const int i = blockIdx.x * blockDim.x + threadIdx.x;
    if (i <= TBL) {
        const float x = -TRNG + (2.0f * TRNG) * (float)i / (float)TBL;
        g_table[i] = 1.0f / (1.0f + expf(-x));
    }
    if (i < K1) g_rstd[i] = 1.0f / stdv[i];
}

// ---------------------------------------------------------------------------
// Convert weights fp32 -> fp16 into scratch (once per launch)
// ---------------------------------------------------------------------------
__global__ __launch_bounds__(256) void convert_weights_kernel(
    const float* __restrict__ w1, const float* __restrict__ w2,
    const float* __restrict__ w3)
{
    constexpr int N1 = H * K1, N2 = H * H, N3E = N3 * H;
    const int stride = gridDim.x * blockDim.x;
    for (int i = blockIdx.x * blockDim.x + threadIdx.x; i < N1 / 4; i += stride) {
        const float4 v = reinterpret_cast<const float4*>(w1)[i];
        __half2* o = reinterpret_cast<__half2*>(g_w1) + i * 2;
        o[0] = __floats2half2_rn(v.x, v.y);
        o[1] = __floats2half2_rn(v.z, v.w);
    }
    for (int i = blockIdx.x * blockDim.x + threadIdx.x; i < N2 / 4; i += stride) {
        const float4 v = reinterpret_cast<const float4*>(w2)[i];
        __half2* o = reinterpret_cast<__half2*>(g_w2) + i * 2;
        o[0] = __floats2half2_rn(v.x, v.y);
        o[1] = __floats2half2_rn(v.z, v.w);
    }
    for (int i = blockIdx.x * blockDim.x + threadIdx.x; i < N3E / 4; i += stride) {
        const float4 v = reinterpret_cast<const float4*>(w3)[i];
        __half2* o = reinterpret_cast<__half2*>(g_w3) + i * 2;
        o[0] = __floats2half2_rn(v.x, v.y);
        o[1] = __floats2half2_rn(v.z, v.w);
    }
}

// ---------------------------------------------------------------------------
// Encoder: spine = fp16(sigmoid((state - mean) * rstd)) via interp table
// ---------------------------------------------------------------------------
__global__ __launch_bounds__(256) void encode_kernel(
    const float* __restrict__ state, const float* __restrict__ mean,
    __half* __restrict__ spine)
{
    __shared__ float tbl[TBL + 4];
    __shared__ float s_mean[K1];
    __shared__ float s_rstd[K1];
    for (int i = threadIdx.x; i <= TBL; i += 256) tbl[i] = g_table[i];
    for (int i = threadIdx.x; i < K1; i += 256) {
        s_mean[i] = mean[i];
        s_rstd[i] = g_rstd[i];
    }
    __syncthreads();

    constexpr float SCALE = (float)TBL / (2.0f * TRNG);
    const int total4 = B_ * K1 / 4;
    for (int idx4 = blockIdx.x * blockDim.x + threadIdx.x; idx4 < total4;
         idx4 += gridDim.x * blockDim.x) {
        const int base = idx4 * 4;
        const int b  = base / K1;
        const int k0 = base - b * K1;
        float v[4];
        #pragma unroll
        for (int j = 0; j < 4; j++) {
            const int k = k0 + j;
            const int d = k / EK;
            const float x = (state[b * SD + d] - s_mean[k]) * s_rstd[k];
            float t = (x + TRNG) * SCALE;
            t = fminf(fmaxf(t, 0.0f), (float)TBL - 0.0001f);
            const int i = (int)t;
            const float f = t - (float)i;
            v[j] = fmaf(f, tbl[i + 1] - tbl[i], tbl[i]);
        }
        __half2 h0 = __floats2half2_rn(v[0], v[1]);
        __half2 h1 = __floats2half2_rn(v[2], v[3]);
        uint2 pk = make_uint2(*reinterpret_cast<uint32_t*>(&h0),
                              *reinterpret_cast<uint32_t*>(&h1));
        *reinterpret_cast<uint2*>(&spine[base]) = pk;
    }
}

// ---------------------------------------------------------------------------
// fp16 mma GEMM: out = act(A @ W^T + bias)
//   A [B_,KDIM] half row-major, W [NDIM,KDIM] half row-major.
//   BM x BN x 64 tiles, 256 threads, 8 warps 2x4 (warp tile 64 x BN/4),
//   3-stage cp.async pipeline, 2 CTAs/SM, ldmatrix fragments, m16n8k16 MMA.
//   OUT_HALF: write __half (feeds next GEMM); else float.
// ---------------------------------------------------------------------------
template <int BN, int NDIM, int KDIM, bool RELU, bool OUT_HALF>
__global__ __launch_bounds__(256, 2) void gemm_f16(
    const __half* __restrict__ A, const __half* __restrict__ W,
    const float* __restrict__ bias, void* __restrict__ out_raw)
{
    constexpr int STRIDE  = (BM + BN) * LDH;     // halves per stage
    constexpr int A_HALVES = BM * LDH;
    constexpr int NT = BN / 32;                  // 8-wide n-tiles per warp
    constexpr int NP = NT / 2;                   // B ldmatrix pairs
    constexpr int nK = KDIM / BK;
    constexpr int KKS = BK / 16;                 // 4 k16 steps per chunk
    extern __shared__ __half smh[];

    const int tid  = threadIdx.x;
    const int lane = tid & 31;
    const int wid  = tid >> 5;
    const int bm = blockIdx.y * BM;
    const int bn = blockIdx.x * BN;
    const int wm = (wid >> 2) * 64;
    const int wn = (wid & 3) * (BN / 4);
    const int ar = lane >> 2;
    const int ac = lane & 3;

    const uint32_t smb = smem_u32(smh);
    // A fragment lanes: 0-7 rows r0-7@k0 | 8-15 rows+8@k0 | 16-23 r0-7@k8 | 24-31 rows+8@k8
    const uint32_t a_lane = smb +
        2u * ((wm + ((lane >> 3) & 1) * 8 + (lane & 7)) * LDH + (lane >> 4) * 8);
    // B fragment lanes: 0-7 n0-7@k0 | 8-15 n0-7@k8 | 16-23 n8-15@k0 | 24-31 n8-15@k8
    const uint32_t b_lane = smb + 2u * A_HALVES +
        2u * ((wn + (lane >> 4) * 8 + (lane & 7)) * LDH + ((lane >> 3) & 1) * 8);

    float acc[4][NT][4];
    #pragma unroll
    for (int i = 0; i < 4; i++)
        #pragma unroll
        for (int j = 0; j < NT; j++)
            #pragma unroll
            for (int m = 0; m < 4; m++) acc[i][j][m] = 0.0f;

    auto load_stage = [&](int s, int kc) {
        __half* As = smh + s * STRIDE;
        __half* Bs = As + A_HALVES;
        const int k0 = kc * BK;
        // rows of 64 halves = 8 x 16B chunks
        #pragma unroll 4
        for (int q = tid; q < BM * 8; q += 256) {
            const int r = q >> 3, c = q & 7;
            cp_async16(smem_u32(As + r * LDH + c * 8),
                       A + (size_t)(bm + r) * KDIM + k0 + c * 8);
        }
        #pragma unroll 4
        for (int q = tid; q < BN * 8; q += 256) {
            const int r = q >> 3, c = q & 7;
            cp_async16(smem_u32(Bs + r * LDH + c * 8),
                       W + (size_t)(bn + r) * KDIM + k0 + c * 8);
        }
    };

    #pragma unroll
    for (int s = 0; s < STAGES - 1; s++) { load_stage(s, s); cp_commit(); }

    for (int k = 0; k < nK; k++) {
        cp_wait_group<STAGES - 2>();
        __syncthreads();

        // Issue next-stage cp.async first (2-chunk latency slack).
        const int kn = k + STAGES - 1;
        if (kn < nK) load_stage(kn % STAGES, kn);
        cp_commit();

        const uint32_t stg = (uint32_t)((k % STAGES) * STRIDE * 2);
        #pragma unroll
        for (int kk = 0; kk < KKS; kk++) {
            uint32_t af[4][4], bf[NT][2];
            #pragma unroll
            for (int tm = 0; tm < 4; tm++)
                ldsm_x4(af[tm][0], af[tm][1], af[tm][2], af[tm][3],
                        a_lane + stg + (uint32_t)(tm * 16 * LDH + kk * 16) * 2);
            #pragma unroll
            for (int tp = 0; tp < NP; tp++)
                ldsm_x4(bf[tp * 2][0], bf[tp * 2][1],
                        bf[tp * 2 + 1][0], bf[tp * 2 + 1][1],
                        b_lane + stg + (uint32_t)(tp * 16 * LDH + kk * 16) * 2);
            #pragma unroll
            for (int tm = 0; tm < 4; tm++)
                #pragma unroll
                for (int tn = 0; tn < NT; tn++)
                    mma_f16(acc[tm][tn], af[tm], bf[tn]);
        }
    }

    // Epilogue: bias + activation; half2 or float2 stores.
    #pragma unroll
    for (int tm = 0; tm < 4; tm++) {
        const int row0 = bm + wm + tm * 16 + ar;
        #pragma unroll
        for (int tn = 0; tn < NT; tn++) {
            const int col = bn + wn + tn * 8 + ac * 2;
            const float bx = bias[col];
            const float by = bias[col + 1];
            float* c = acc[tm][tn];
            float2 v0, v1;
            v0.x = c[0] + bx; v0.y = c[1] + by;
            v1.x = c[2] + bx; v1.y = c[3] + by;
            if (RELU) {
                v0.x = v0.x > 0.0f ? v0.x : 0.0f;
                v0.y = v0.y > 0.0f ? v0.y : 0.0f;
                v1.x = v1.x > 0.0f ? v1.x : 0.0f;
                v1.y = v1.y > 0.0f ? v1.y : 0.0f;
            }
            if (OUT_HALF) {
                __half* out = (__half*)out_raw;
                *reinterpret_cast<__half2*>(&out[(size_t)row0 * NDIM + col]) =
                    __floats2half2_rn(v0.x, v0.y);
                *reinterpret_cast<__half2*>(&out[(size_t)(row0 + 8) * NDIM + col]) =
                    __floats2half2_rn(v1.x, v1.y);
            } else {
                float* out = (float*)out_raw;
                *reinterpret_cast<float2*>(&out[(size_t)row0 * NDIM + col]) = v0;
                *reinterpret_cast<float2*>(&out[(size_t)(row0 + 8) * NDIM + col]) = v1;
            }
        }
    }
}

// ---------------------------------------------------------------------------
// Decoder: out[b,a] = tanh(sum_j a3[b, a*DK+j] * Wd[a*DK+j] + bd[a])
// ---------------------------------------------------------------------------
__global__ __launch_bounds__(256) void decode_kernel(
    const float* __restrict__ a3, const float* __restrict__ Wd,
    const float* __restrict__ bd, float* __restrict__ out)
{
    const int idx = blockIdx.x * blockDim.x + threadIdx.x;
    if (idx >= B_ * AD) return;
    const int b = idx >> 5;
    const int a = idx & 31;
    float s = bd[a];
    #pragma unroll
    for (int j = 0; j < DK; j++)
        s = fmaf(a3[b * N3 + a * DK + j], Wd[a * DK + j], s);
    out[idx] = tanhf(s);
}

// ---------------------------------------------------------------------------
extern "C" void kernel_launch(void* const* d_in, const int* in_sizes, int n_in,
                              void* d_out, int out_size)
{
    const float* state = (const float*)d_in[0];
    const float* mean  = (const float*)d_in[1];
    const float* stdv  = (const float*)d_in[2];
    const float* W1    = (const float*)d_in[3];
    const float* b1    = (const float*)d_in[4];
    const float* W2    = (const float*)d_in[5];
    const float* b2    = (const float*)d_in[6];
    const float* W3    = (const float*)d_in[7];
    const float* b3    = (const float*)d_in[8];
    const float* Wd    = (const float*)d_in[9];
    const float* bd    = (const float*)d_in[10];
    float* out = (float*)d_out;

    __half *spine, *h1, *h2, *w1h, *w2h, *w3h;
    float *a3;
    cudaGetSymbolAddress((void**)&spine, g_spine);
    cudaGetSymbolAddress((void**)&h1, g_h1);
    cudaGetSymbolAddress((void**)&h2, g_h2);
    cudaGetSymbolAddress((void**)&a3, g_a3);
    cudaGetSymbolAddress((void**)&w1h, g_w1);
    cudaGetSymbolAddress((void**)&w2h, g_w2);
    cudaGetSymbolAddress((void**)&w3h, g_w3);

    constexpr int SMEM_BIG = STAGES * (BM + 128) * LDH * 2;  // 110592
    constexpr int SMEM_G3  = STAGES * (BM + 64)  * LDH * 2;  //  82944
    static bool attr_done = false;
    if (!attr_done) {
        cudaFuncSetAttribute(gemm_f16<128, H, K1, true, true>,
                             cudaFuncAttributeMaxDynamicSharedMemorySize, SMEM_BIG);
        cudaFuncSetAttribute(gemm_f16<128, H, H, true, true>,
                             cudaFuncAttributeMaxDynamicSharedMemorySize, SMEM_BIG);
        cudaFuncSetAttribute(gemm_f16<64, N3, H, false, false>,
                             cudaFuncAttributeMaxDynamicSharedMemorySize, SMEM_G3);
        attr_done = true;
    }

    init_tables_kernel<<<(TBL + 256) / 256, 256>>>(stdv);
    convert_weights_kernel<<<1024, 256>>>(W1, W2, W3);
    encode_kernel<<<2048, 256>>>(state, mean, spine);

    gemm_f16<128, H, K1, true, true>
        <<<dim3(H / 128, B_ / BM), 256, SMEM_BIG>>>(spine, w1h, b1, h1);
    gemm_f16<128, H, H, true, true>
        <<<dim3(H / 128, B_ / BM), 256, SMEM_BIG>>>(h1, w2h, b2, h2);
    gemm_f16<64, N3, H, false, false>
        <<<dim3(N3 / 64, B_ / BM), 256, SMEM_G3>>>(h2, w3h, b3, a3);

    decode_kernel<<<(B_ * AD + 255) / 256, 256>>>(a3, Wd, bd, out);
}

// round 14
// speedup vs baseline: 2.4055x; 1.1158x over previous
#include <cuda_runtime.h>
#include <cuda_fp16.h>
#include <math.h>
#include <stdint.h>

// ---------------------------------------------------------------------------
// Problem constants
// ---------------------------------------------------------------------------
namespace {
constexpr int B_  = 16384;
constexpr int SD  = 128;
constexpr int EK  = 10;
constexpr int K1  = SD * EK;   // 1280
constexpr int H   = 2048;
constexpr int AD  = 32;
constexpr int DK  = 10;

constexpr int BM  = 128;
constexpr int BK  = 64;            // halves per chunk (4 k16 steps)
constexpr int LDH = BK + 8;        // 72-half (144B) smem row stride: conflict-free
constexpr int STAGES = 3;

constexpr int TBL    = 4096;
constexpr float TRNG = 14.0f;
}

// Scratch (no cudaMalloc allowed) — ONLY accessed via cudaGetSymbolAddress
__device__ __half g_spine[B_ * K1];
__device__ __half g_h1[B_ * H];
__device__ __half g_h2[B_ * H];
__device__ __half g_w1[H * K1];
__device__ __half g_w2[H * H];
__device__ __half g_weff[AD * H];   // folded W3*Wd  [32, 2048]
__device__ float  g_beff[AD];       // folded bias
__device__ float  g_table[TBL + 1];
__device__ float  g_rstd[K1];

// ---------------------------------------------------------------------------
// PTX helpers (sm_80+ only — harness targets compute_100, no tcgen05)
// ---------------------------------------------------------------------------
__device__ __forceinline__ uint32_t smem_u32(const void* p) {
    uint32_t a;
    asm("{ .reg .u64 t; cvta.to.shared.u64 t, %1; cvt.u32.u64 %0, t; }"
        : "=r"(a) : "l"(p));
    return a;
}
__device__ __forceinline__ void cp_async16(uint32_t dst, const void* src) {
    asm volatile("cp.async.cg.shared.global [%0], [%1], 16;\n"
                 :: "r"(dst), "l"(src));
}
__device__ __forceinline__ void cp_commit() {
    asm volatile("cp.async.commit_group;\n" ::: "memory");
}
template <int N>
__device__ __forceinline__ void cp_wait_group() {
    asm volatile("cp.async.wait_group %0;\n" :: "n"(N) : "memory");
}
__device__ __forceinline__ void ldsm_x4(uint32_t& r0, uint32_t& r1,
                                        uint32_t& r2, uint32_t& r3,
                                        uint32_t addr) {
    asm volatile(
        "ldmatrix.sync.aligned.m8n8.x4.shared.b16 {%0,%1,%2,%3}, [%4];"
        : "=r"(r0), "=r"(r1), "=r"(r2), "=r"(r3) : "r"(addr));
}
// fp16 MMA, fp32 accumulate: m16n8k16
__device__ __forceinline__ void mma_f16(float* c, const uint32_t* a,
                                        const uint32_t* b) {
    asm volatile(
        "mma.sync.aligned.m16n8k16.row.col.f32.f16.f16.f32 "
        "{%0,%1,%2,%3}, {%4,%5,%6,%7}, {%8,%9}, {%0,%1,%2,%3};"
        : "+f"(c[0]), "+f"(c[1]), "+f"(c[2]), "+f"(c[3])
        : "r"(a[0]), "r"(a[1]), "r"(a[2]), "r"(a[3]), "r"(b[0]), "r"(b[1]));
}

// ---------------------------------------------------------------------------
// Init: sigmoid table + reciprocal std
// ---------------------------------------------------------------------------
__global__ void init_tables_kernel(const float* __restrict__ stdv,
                                   float* __restrict__ table,
                                   float* __restrict__ rstd) {
    const int i = blockIdx.x * blockDim.x + threadIdx.x;
    if (i <= TBL) {
        const float x = -TRNG + (2.0f * TRNG) * (float)i / (float)TBL;
        table[i] = 1.0f / (1.0f + expf(-x));
    }
    if (i < K1) rstd[i] = 1.0f / stdv[i];
}

// ---------------------------------------------------------------------------
// Convert W1/W2 fp32 -> fp16 (once per launch)
// ---------------------------------------------------------------------------
__global__ __launch_bounds__(256) void convert_weights_kernel(
    const float* __restrict__ w1, const float* __restrict__ w2,
    __half* __restrict__ w1h, __half* __restrict__ w2h)
{
    constexpr int N1 = H * K1, N2 = H * H;
    const int stride = gridDim.x * blockDim.x;
    for (int i = blockIdx.x * blockDim.x + threadIdx.x; i < N1 / 4; i += stride) {
        const float4 v = reinterpret_cast<const float4*>(w1)[i];
        __half2* o = reinterpret_cast<__half2*>(w1h) + i * 2;
        o[0] = __floats2half2_rn(v.x, v.y);
        o[1] = __floats2half2_rn(v.z, v.w);
    }
    for (int i = blockIdx.x * blockDim.x + threadIdx.x; i < N2 / 4; i += stride) {
        const float4 v = reinterpret_cast<const float4*>(w2)[i];
        __half2* o = reinterpret_cast<__half2*>(w2h) + i * 2;
        o[0] = __floats2half2_rn(v.x, v.y);
        o[1] = __floats2half2_rn(v.z, v.w);
    }
}

// ---------------------------------------------------------------------------
// Fold decoder into layer-3 weights (fp32 accumulate from ORIGINAL fp32 W3):
//   Weff[a,k] = sum_j Wd[a,j] * W3[a*DK+j, k]
//   beff[a]   = sum_j Wd[a,j] * b3[a*DK+j] + bd[a]
// ---------------------------------------------------------------------------
__global__ __launch_bounds__(256) void fold_w3_kernel(
    const float* __restrict__ w3, const float* __restrict__ b3,
    const float* __restrict__ wd, const float* __restrict__ bd,
    __half* __restrict__ weff, float* __restrict__ beff)
{
    const int idx = blockIdx.x * blockDim.x + threadIdx.x;   // a*H + k
    if (idx >= AD * H) return;
    const int a = idx >> 11;          // / H
    const int k = idx & (H - 1);
    float s = 0.0f;
    #pragma unroll
    for (int j = 0; j < DK; j++)
        s = fmaf(wd[a * DK + j], w3[(size_t)(a * DK + j) * H + k], s);
    weff[idx] = __float2half(s);
    if (k == 0) {
        float b = bd[a];
        #pragma unroll
        for (int j = 0; j < DK; j++)
            b = fmaf(wd[a * DK + j], b3[a * DK + j], b);
        beff[a] = b;
    }
}

// ---------------------------------------------------------------------------
// Encoder: spine = fp16(sigmoid((state - mean) * rstd)) via interp table
// ---------------------------------------------------------------------------
__global__ __launch_bounds__(256) void encode_kernel(
    const float* __restrict__ state, const float* __restrict__ mean,
    const float* __restrict__ table, const float* __restrict__ rstd,
    __half* __restrict__ spine)
{
    __shared__ float tbl[TBL + 4];
    __shared__ float s_mean[K1];
    __shared__ float s_rstd[K1];
    for (int i = threadIdx.x; i <= TBL; i += 256) tbl[i] = table[i];
    for (int i = threadIdx.x; i < K1; i += 256) {
        s_mean[i] = mean[i];
        s_rstd[i] = rstd[i];
    }
    __syncthreads();

    constexpr float SCALE = (float)TBL / (2.0f * TRNG);
    const int total4 = B_ * K1 / 4;
    for (int idx4 = blockIdx.x * blockDim.x + threadIdx.x; idx4 < total4;
         idx4 += gridDim.x * blockDim.x) {
        const int base = idx4 * 4;
        const int b  = base / K1;
        const int k0 = base - b * K1;
        float v[4];
        #pragma unroll
        for (int j = 0; j < 4; j++) {
            const int k = k0 + j;
            const int d = k / EK;
            const float x = (state[b * SD + d] - s_mean[k]) * s_rstd[k];
            float t = (x + TRNG) * SCALE;
            t = fminf(fmaxf(t, 0.0f), (float)TBL - 0.0001f);
            const int i = (int)t;
            const float f = t - (float)i;
            v[j] = fmaf(f, tbl[i + 1] - tbl[i], tbl[i]);
        }
        __half2 h0 = __floats2half2_rn(v[0], v[1]);
        __half2 h1 = __floats2half2_rn(v[2], v[3]);
        uint2 pk = make_uint2(*reinterpret_cast<uint32_t*>(&h0),
                              *reinterpret_cast<uint32_t*>(&h1));
        *reinterpret_cast<uint2*>(&spine[base]) = pk;
    }
}

// ---------------------------------------------------------------------------
// fp16 mma GEMM (layers 1/2): out = relu(A @ W^T + bias) as fp16.
//   BM x 128 x 64 tiles, 256 threads, 8 warps 2x4, 3-stage cp.async, 2 CTA/SM.
// ---------------------------------------------------------------------------
template <int BN, int NDIM, int KDIM>
__global__ __launch_bounds__(256, 2) void gemm_f16(
    const __half* __restrict__ A, const __half* __restrict__ W,
    const float* __restrict__ bias, __half* __restrict__ out)
{
    constexpr int STRIDE  = (BM + BN) * LDH;
    constexpr int A_HALVES = BM * LDH;
    constexpr int NT = BN / 32;
    constexpr int NP = NT / 2;
    constexpr int nK = KDIM / BK;
    constexpr int KKS = BK / 16;
    extern __shared__ __half smh[];

    const int tid  = threadIdx.x;
    const int lane = tid & 31;
    const int wid  = tid >> 5;
    const int bm = blockIdx.y * BM;
    const int bn = blockIdx.x * BN;
    const int wm = (wid >> 2) * 64;
    const int wn = (wid & 3) * (BN / 4);
    const int ar = lane >> 2;
    const int ac = lane & 3;

    const uint32_t smb = smem_u32(smh);
    const uint32_t a_lane = smb +
        2u * ((wm + ((lane >> 3) & 1) * 8 + (lane & 7)) * LDH + (lane >> 4) * 8);
    const uint32_t b_lane = smb + 2u * A_HALVES +
        2u * ((wn + (lane >> 4) * 8 + (lane & 7)) * LDH + ((lane >> 3) & 1) * 8);

    float acc[4][NT][4];
    #pragma unroll
    for (int i = 0; i < 4; i++)
        #pragma unroll
        for (int j = 0; j < NT; j++)
            #pragma unroll
            for (int m = 0; m < 4; m++) acc[i][j][m] = 0.0f;

    auto load_stage = [&](int s, int kc) {
        __half* As = smh + s * STRIDE;
        __half* Bs = As + A_HALVES;
        const int k0 = kc * BK;
        #pragma unroll 4
        for (int q = tid; q < BM * 8; q += 256) {
            const int r = q >> 3, c = q & 7;
            cp_async16(smem_u32(As + r * LDH + c * 8),
                       A + (size_t)(bm + r) * KDIM + k0 + c * 8);
        }
        #pragma unroll 4
        for (int q = tid; q < BN * 8; q += 256) {
            const int r = q >> 3, c = q & 7;
            cp_async16(smem_u32(Bs + r * LDH + c * 8),
                       W + (size_t)(bn + r) * KDIM + k0 + c * 8);
        }
    };

    #pragma unroll
    for (int s = 0; s < STAGES - 1; s++) { load_stage(s, s); cp_commit(); }

    for (int k = 0; k < nK; k++) {
        cp_wait_group<STAGES - 2>();
        __syncthreads();

        const int kn = k + STAGES - 1;
        if (kn < nK) load_stage(kn % STAGES, kn);
        cp_commit();

        const uint32_t stg = (uint32_t)((k % STAGES) * STRIDE * 2);
        #pragma unroll
        for (int kk = 0; kk < KKS; kk++) {
            uint32_t af[4][4], bf[NT][2];
            #pragma unroll
            for (int tm = 0; tm < 4; tm++)
                ldsm_x4(af[tm][0], af[tm][1], af[tm][2], af[tm][3],
                        a_lane + stg + (uint32_t)(tm * 16 * LDH + kk * 16) * 2);
            #pragma unroll
            for (int tp = 0; tp < NP; tp++)
                ldsm_x4(bf[tp * 2][0], bf[tp * 2][1],
                        bf[tp * 2 + 1][0], bf[tp * 2 + 1][1],
                        b_lane + stg + (uint32_t)(tp * 16 * LDH + kk * 16) * 2);
            #pragma unroll
            for (int tm = 0; tm < 4; tm++)
                #pragma unroll
                for (int tn = 0; tn < NT; tn++)
                    mma_f16(acc[tm][tn], af[tm], bf[tn]);
        }
    }

    #pragma unroll
    for (int tm = 0; tm < 4; tm++) {
        const int row0 = bm + wm + tm * 16 + ar;
        #pragma unroll
        for (int tn = 0; tn < NT; tn++) {
            const int col = bn + wn + tn * 8 + ac * 2;
            const float bx = bias[col];
            const float by = bias[col + 1];
            float* c = acc[tm][tn];
            float2 v0, v1;
            v0.x = c[0] + bx; v0.y = c[1] + by;
            v1.x = c[2] + bx; v1.y = c[3] + by;
            v0.x = v0.x > 0.0f ? v0.x : 0.0f;
            v0.y = v0.y > 0.0f ? v0.y : 0.0f;
            v1.x = v1.x > 0.0f ? v1.x : 0.0f;
            v1.y = v1.y > 0.0f ? v1.y : 0.0f;
            *reinterpret_cast<__half2*>(&out[(size_t)row0 * NDIM + col]) =
                __floats2half2_rn(v0.x, v0.y);
            *reinterpret_cast<__half2*>(&out[(size_t)(row0 + 8) * NDIM + col]) =
                __floats2half2_rn(v1.x, v1.y);
        }
    }
}

// ---------------------------------------------------------------------------
// Fused last layer: out[b,a] = tanh(h2[b,:] @ Weff[a,:] + beff[a]), a<32.
//   BM=128 x BN=32 x 64 tiles, 256 threads, 8 warps M-split (warp tile 16x32).
// ---------------------------------------------------------------------------
__global__ __launch_bounds__(256, 2) void gemm_last(
    const __half* __restrict__ A, const __half* __restrict__ weff,
    const float* __restrict__ beff, float* __restrict__ out)
{
    constexpr int BN = 32;
    constexpr int STRIDE  = (BM + BN) * LDH;
    constexpr int A_HALVES = BM * LDH;
    constexpr int NT = 4;                      // four 8-wide n-tiles (full 32)
    constexpr int nK = H / BK;                 // 32
    constexpr int KKS = BK / 16;
    extern __shared__ __half smh[];

    const int tid  = threadIdx.x;
    const int lane = tid & 31;
    const int wid  = tid >> 5;
    const int bm = blockIdx.y * BM;
    const int wm = wid * 16;                   // 8 warps stacked in M
    const int ar = lane >> 2;
    const int ac = lane & 3;

    const uint32_t smb = smem_u32(smh);
    const uint32_t a_lane = smb +
        2u * ((wm + ((lane >> 3) & 1) * 8 + (lane & 7)) * LDH + (lane >> 4) * 8);
    const uint32_t b_lane = smb + 2u * A_HALVES +
        2u * (((lane >> 4) * 8 + (lane & 7)) * LDH + ((lane >> 3) & 1) * 8);

    float acc[NT][4];
    #pragma unroll
    for (int j = 0; j < NT; j++)
        #pragma unroll
        for (int m = 0; m < 4; m++) acc[j][m] = 0.0f;

    auto load_stage = [&](int s, int kc) {
        __half* As = smh + s * STRIDE;
        __half* Bs = As + A_HALVES;
        const int k0 = kc * BK;
        #pragma unroll 4
        for (int q = tid; q < BM * 8; q += 256) {
            const int r = q >> 3, c = q & 7;
            cp_async16(smem_u32(As + r * LDH + c * 8),
                       A + (size_t)(bm + r) * H + k0 + c * 8);
        }
        {   // BN=32 rows: exactly 256 chunks
            const int r = tid >> 3, c = tid & 7;
            cp_async16(smem_u32(Bs + r * LDH + c * 8),
                       weff + (size_t)r * H + k0 + c * 8);
        }
    };

    #pragma unroll
    for (int s = 0; s < STAGES - 1; s++) { load_stage(s, s); cp_commit(); }

    for (int k = 0; k < nK; k++) {
        cp_wait_group<STAGES - 2>();
        __syncthreads();

        const int kn = k + STAGES - 1;
        if (kn < nK) load_stage(kn % STAGES, kn);
        cp_commit();

        const uint32_t stg = (uint32_t)((k % STAGES) * STRIDE * 2);
        #pragma unroll
        for (int kk = 0; kk < KKS; kk++) {
            uint32_t af[4], bf[NT][2];
            ldsm_x4(af[0], af[1], af[2], af[3],
                    a_lane + stg + (uint32_t)(kk * 16) * 2);
            #pragma unroll
            for (int tp = 0; tp < NT / 2; tp++)
                ldsm_x4(bf[tp * 2][0], bf[tp * 2][1],
                        bf[tp * 2 + 1][0], bf[tp * 2 + 1][1],
                        b_lane + stg + (uint32_t)(tp * 16 * LDH + kk * 16) * 2);
            #pragma unroll
            for (int tn = 0; tn < NT; tn++)
                mma_f16(acc[tn], af, bf[tn]);
        }
    }

    const int row0 = bm + wm + ar;
    #pragma unroll
    for (int tn = 0; tn < NT; tn++) {
        const int col = tn * 8 + ac * 2;
        float2 v0, v1;
        v0.x = tanhf(acc[tn][0] + beff[col]);
        v0.y = tanhf(acc[tn][1] + beff[col + 1]);
        v1.x = tanhf(acc[tn][2] + beff[col]);
        v1.y = tanhf(acc[tn][3] + beff[col + 1]);
        *reinterpret_cast<float2*>(&out[(size_t)row0 * AD + col]) = v0;
        *reinterpret_cast<float2*>(&out[(size_t)(row0 + 8) * AD + col]) = v1;
    }
}

// ---------------------------------------------------------------------------
extern "C" void kernel_launch(void* const* d_in, const int* in_sizes, int n_in,
                              void* d_out, int out_size)
{
    const float* state = (const float*)d_in[0];
    const float* mean  = (const float*)d_in[1];
    const float* stdv  = (const float*)d_in[2];
    const float* W1    = (const float*)d_in[3];
    const float* b1    = (const float*)d_in[4];
    const float* W2    = (const float*)d_in[5];
    const float* b2    = (const float*)d_in[6];
    const float* W3    = (const float*)d_in[7];
    const float* b3    = (const float*)d_in[8];
    const float* Wd    = (const float*)d_in[9];
    const float* bd    = (const float*)d_in[10];
    float* out = (float*)d_out;

    __half *spine, *h1, *h2, *w1h, *w2h, *weff;
    float *beff, *table, *rstd;
    cudaGetSymbolAddress((void**)&spine, g_spine);
    cudaGetSymbolAddress((void**)&h1,    g_h1);
    cudaGetSymbolAddress((void**)&h2,    g_h2);
    cudaGetSymbolAddress((void**)&w1h,   g_w1);
    cudaGetSymbolAddress((void**)&w2h,   g_w2);
    cudaGetSymbolAddress((void**)&weff,  g_weff);
    cudaGetSymbolAddress((void**)&beff,  g_beff);
    cudaGetSymbolAddress((void**)&table, g_table);
    cudaGetSymbolAddress((void**)&rstd,  g_rstd);

    constexpr int SMEM_BIG  = STAGES * (BM + 128) * LDH * 2;  // 110592
    constexpr int SMEM_LAST = STAGES * (BM + 32)  * LDH * 2;  //  69120
    static bool attr_done = false;
    if (!attr_done) {
        cudaFuncSetAttribute(gemm_f16<128, H, K1>,
                             cudaFuncAttributeMaxDynamicSharedMemorySize, SMEM_BIG);
        cudaFuncSetAttribute(gemm_f16<128, H, H>,
                             cudaFuncAttributeMaxDynamicSharedMemorySize, SMEM_BIG);
        cudaFuncSetAttribute(gemm_last,
                             cudaFuncAttributeMaxDynamicSharedMemorySize, SMEM_LAST);
        attr_done = true;
    }

    init_tables_kernel<<<(TBL + 256) / 256, 256>>>(stdv, table, rstd);
    convert_weights_kernel<<<1024, 256>>>(W1, W2, w1h, w2h);
    fold_w3_kernel<<<(AD * H + 255) / 256, 256>>>(W3, b3, Wd, bd, weff, beff);
    encode_kernel<<<2048, 256>>>(state, mean, table, rstd, spine);

    gemm_f16<128, H, K1>
        <<<dim3(H / 128, B_ / BM), 256, SMEM_BIG>>>(spine, w1h, b1, h1);
    gemm_f16<128, H, H>
        <<<dim3(H / 128, B_ / BM), 256, SMEM_BIG>>>(h1, w2h, b2, h2);
    gemm_last<<<dim3(1, B_ / BM), 256, SMEM_LAST>>>(h2, weff, beff, out);
}